// round 16
// baseline (speedup 1.0000x reference)
#include <cuda_runtime.h>
#include <cuda_bf16.h>
#include <cstdint>

#define B_  4
#define S_  2048
#define D_  1024
#define H_  16
#define DK_ 64
#define DP_ 512   // D/2 packed u32 per row

// Scratch (no cudaMalloc; __device__ globals), all bf16 hi/lo packed u32.
__device__ uint32_t g_Xqh[(size_t)B_ * S_ * DP_];
__device__ uint32_t g_Xql[(size_t)B_ * S_ * DP_];
__device__ uint32_t g_Xkh[(size_t)B_ * S_ * DP_];
__device__ uint32_t g_Xkl[(size_t)B_ * S_ * DP_];
__device__ uint32_t g_Xvh[(size_t)B_ * S_ * DP_];
__device__ uint32_t g_Xvl[(size_t)B_ * S_ * DP_];
__device__ uint32_t g_Wqh[(size_t)D_ * DP_];
__device__ uint32_t g_Wql[(size_t)D_ * DP_];
__device__ uint32_t g_Wkh[(size_t)D_ * DP_];
__device__ uint32_t g_Wkl[(size_t)D_ * DP_];
__device__ uint32_t g_Wvh[(size_t)D_ * DP_];
__device__ uint32_t g_Wvl[(size_t)D_ * DP_];
__device__ uint32_t g_Woh[(size_t)D_ * DP_];
__device__ uint32_t g_Wol[(size_t)D_ * DP_];
__device__ uint32_t g_Qh[(size_t)B_ * S_ * DP_];
__device__ uint32_t g_Ql[(size_t)B_ * S_ * DP_];
__device__ uint32_t g_Kh[(size_t)B_ * S_ * DP_];
__device__ uint32_t g_Kl[(size_t)B_ * S_ * DP_];
__device__ uint32_t g_Vh[(size_t)B_ * S_ * DP_];
__device__ uint32_t g_Vl[(size_t)B_ * S_ * DP_];
__device__ uint32_t g_Oh[(size_t)B_ * S_ * DP_];
__device__ uint32_t g_Ol[(size_t)B_ * S_ * DP_];

// ===========================================================================
// Common helpers
// ===========================================================================
__device__ __forceinline__ uint32_t smem_u32(const void* p)
{
    uint32_t a;
    asm("{ .reg .u64 t; cvta.to.shared.u64 t, %1; cvt.u32.u64 %0, t; }"
        : "=r"(a) : "l"(p));
    return a;
}

__device__ __forceinline__ uint32_t pack_bf16(__nv_bfloat16 a, __nv_bfloat16 b)
{
    return (uint32_t)__bfloat16_as_ushort(a) |
           ((uint32_t)__bfloat16_as_ushort(b) << 16);
}

// NOT volatile: pure computation; lets nvcc/ptxas software-pipeline and
// interleave independent mmas (the R15 serialization fix).
__device__ __forceinline__ void mma_bf16(float4& c,
    uint32_t a0, uint32_t a1, uint32_t a2, uint32_t a3,
    uint32_t b0, uint32_t b1)
{
    asm("mma.sync.aligned.m16n8k16.row.col.f32.bf16.bf16.f32 "
        "{%0,%1,%2,%3}, {%4,%5,%6,%7}, {%8,%9}, {%0,%1,%2,%3};"
        : "+f"(c.x), "+f"(c.y), "+f"(c.z), "+f"(c.w)
        : "r"(a0), "r"(a1), "r"(a2), "r"(a3), "r"(b0), "r"(b1));
}

__device__ __forceinline__ void ldm_x4(uint32_t& r0, uint32_t& r1,
                                       uint32_t& r2, uint32_t& r3, uint32_t a)
{
    asm volatile(
        "ldmatrix.sync.aligned.m8n8.x4.shared.b16 {%0,%1,%2,%3}, [%4];"
        : "=r"(r0), "=r"(r1), "=r"(r2), "=r"(r3) : "r"(a));
}

__device__ __forceinline__ void ldm_x4_t(uint32_t& r0, uint32_t& r1,
                                         uint32_t& r2, uint32_t& r3, uint32_t a)
{
    asm volatile(
        "ldmatrix.sync.aligned.m8n8.x4.trans.shared.b16 {%0,%1,%2,%3}, [%4];"
        : "=r"(r0), "=r"(r1), "=r"(r2), "=r"(r3) : "r"(a));
}

__device__ __forceinline__ void cpa16(uint32_t dst, const void* src)
{
    asm volatile("cp.async.ca.shared.global [%0], [%1], 16;"
                 :: "r"(dst), "l"(src) : "memory");
}

// Fast exp on the FMA pipe (no MUFU).
__device__ __forceinline__ float fexp(float x)
{
    float t = fmaxf(x * 1.4426950408889634f, -126.0f);
    float z = t + 12582912.0f;
    int  ei = __float_as_int(z) - 0x4B400000;
    float f = t - (z - 12582912.0f);
    float p = fmaf(0.0013333558f, f, 0.0096181291f);
    p = fmaf(p, f, 0.0555041087f);
    p = fmaf(p, f, 0.2402265069f);
    p = fmaf(p, f, 0.6931471806f);
    p = fmaf(p, f, 1.0f);
    return __int_as_float(__float_as_int(p) + (ei << 23));
}

// ===========================================================================
// Split kernel: fp32 -> packed bf16 hi/lo (Dekker), memory-bound.
// ===========================================================================
__global__ void __launch_bounds__(256)
split_kernel(const float* __restrict__ src, uint32_t* __restrict__ hi,
             uint32_t* __restrict__ lo, int n4)
{
    int i = blockIdx.x * 256 + threadIdx.x;
    if (i >= n4) return;
    float4 v = reinterpret_cast<const float4*>(src)[i];
    __nv_bfloat16 hx = __float2bfloat16(v.x), hy = __float2bfloat16(v.y);
    __nv_bfloat16 hz = __float2bfloat16(v.z), hw = __float2bfloat16(v.w);
    reinterpret_cast<uint2*>(hi)[i] =
        make_uint2(pack_bf16(hx, hy), pack_bf16(hz, hw));
    reinterpret_cast<uint2*>(lo)[i] = make_uint2(
        pack_bf16(__float2bfloat16(v.x - __bfloat162float(hx)),
                  __float2bfloat16(v.y - __bfloat162float(hy))),
        pack_bf16(__float2bfloat16(v.z - __bfloat162float(hz)),
                  __float2bfloat16(v.w - __bfloat162float(hw))));
}

// ===========================================================================
// bf16x3 GEMM on pre-split operands, type-major mma ordering.
// ===========================================================================
#define GST2 20
#define GBUF (128 * GST2)
#define GSTG (4 * GBUF)

__device__ __forceinline__ uint32_t a_off2(int lane)
{
    return (uint32_t)(((lane & 15) * GST2 + (lane >> 4) * 4) * 4);
}
__device__ __forceinline__ uint32_t b_off2(int lane)
{
    return (uint32_t)((((lane & 7) + ((lane >> 4) << 3)) * GST2 +
                       ((lane >> 3) & 1) * 4) * 4);
}

template<bool SPLIT>
__global__ void __launch_bounds__(256, 2)
gemm_sp_kernel(const uint32_t* __restrict__ Ahg, const uint32_t* __restrict__ Alg,
               const uint32_t* __restrict__ Bhg, const uint32_t* __restrict__ Blg,
               float* __restrict__ C, uint32_t* __restrict__ Chi,
               uint32_t* __restrict__ Clo, int M, int N)
{
    extern __shared__ uint32_t smu[];
    const uint32_t sb = smem_u32(smu);

    const int tid  = threadIdx.x;
    const int lane = tid & 31;
    const int warp = tid >> 5;
    const int g    = lane >> 2;
    const int tig  = lane & 3;
    const int wm   = (warp >> 2) * 64;
    const int wn   = (warp & 3) * 32;
    const int m0   = blockIdx.y * 128;
    const int n0   = blockIdx.x * 128;
    const uint32_t ao = a_off2(lane);
    const uint32_t bo = b_off2(lane);

    auto stage = [&](int kc, int ss) {
        const uint32_t tb = sb + (uint32_t)(ss * GSTG) * 4;
        #pragma unroll
        for (int i = 0; i < 8; i++) {
            int idx = tid + i * 256;
            int bf  = idx >> 9;
            int rem = idx & 511;
            int r   = rem >> 2;
            int c   = (rem & 3) * 4;
            const uint32_t* base =
                (bf == 0) ? Ahg + (size_t)(m0 + r) * DP_ :
                (bf == 1) ? Alg + (size_t)(m0 + r) * DP_ :
                (bf == 2) ? Bhg + (size_t)(n0 + r) * DP_ :
                            Blg + (size_t)(n0 + r) * DP_;
            cpa16(tb + (uint32_t)(bf * GBUF + r * GST2 + c) * 4,
                  base + kc + c);
        }
    };

    float4 acc[4][4];
    #pragma unroll
    for (int i = 0; i < 4; i++)
        #pragma unroll
        for (int j = 0; j < 4; j++) acc[i][j] = make_float4(0.f, 0.f, 0.f, 0.f);

    stage(0, 0);
    asm volatile("cp.async.commit_group;" ::: "memory");
    int ps = 0;

    for (int kc = 0; kc < DP_; kc += 16) {
        __syncthreads();
        const bool more = (kc + 16 < DP_);
        if (more) {
            stage(kc + 16, ps ^ 1);
            asm volatile("cp.async.commit_group;" ::: "memory");
            asm volatile("cp.async.wait_group 1;" ::: "memory");
        } else {
            asm volatile("cp.async.wait_group 0;" ::: "memory");
        }
        __syncthreads();

        const uint32_t tb  = sb + (uint32_t)(ps * GSTG) * 4;
        const uint32_t sAh = tb;
        const uint32_t sAl = tb + (uint32_t)GBUF * 4;
        const uint32_t sBh = tb + (uint32_t)(2 * GBUF) * 4;
        const uint32_t sBl = tb + (uint32_t)(3 * GBUF) * 4;

        #pragma unroll
        for (int ks = 0; ks < 2; ks++) {
            uint32_t bh[4][2], bl[4][2];
            #pragma unroll
            for (int tp = 0; tp < 2; tp++) {
                uint32_t ba = (uint32_t)(((wn + tp * 16) * GST2 + ks * 8) * 4) + bo;
                ldm_x4(bh[2 * tp][0], bh[2 * tp][1],
                       bh[2 * tp + 1][0], bh[2 * tp + 1][1], sBh + ba);
                ldm_x4(bl[2 * tp][0], bl[2 * tp][1],
                       bl[2 * tp + 1][0], bl[2 * tp + 1][1], sBl + ba);
            }
            #pragma unroll
            for (int tm = 0; tm < 4; tm++) {
                uint32_t aa = (uint32_t)(((wm + tm * 16) * GST2 + ks * 8) * 4) + ao;
                uint32_t ah0, ah1, ah2, ah3, al0, al1, al2, al3;
                ldm_x4(ah0, ah1, ah2, ah3, sAh + aa);
                ldm_x4(al0, al1, al2, al3, sAl + aa);
                // type-major: chain distance 4 (independent tn between reuse)
                #pragma unroll
                for (int tn = 0; tn < 4; tn++)
                    mma_bf16(acc[tm][tn], ah0, ah1, ah2, ah3,
                             bh[tn][0], bh[tn][1]);
                #pragma unroll
                for (int tn = 0; tn < 4; tn++)
                    mma_bf16(acc[tm][tn], ah0, ah1, ah2, ah3,
                             bl[tn][0], bl[tn][1]);
                #pragma unroll
                for (int tn = 0; tn < 4; tn++)
                    mma_bf16(acc[tm][tn], al0, al1, al2, al3,
                             bh[tn][0], bh[tn][1]);
            }
        }
        ps ^= 1;
    }

    #pragma unroll
    for (int tm = 0; tm < 4; tm++) {
        #pragma unroll
        for (int tn = 0; tn < 4; tn++) {
            int row = m0 + wm + tm * 16 + g;
            int col = n0 + wn + tn * 8 + 2 * tig;
            if (SPLIT) {
                float4 c4v = acc[tm][tn];
                size_t i0 = (size_t)row * DP_ + (col >> 1);
                size_t i1 = (size_t)(row + 8) * DP_ + (col >> 1);
                __nv_bfloat16 hx = __float2bfloat16(c4v.x);
                __nv_bfloat16 hy = __float2bfloat16(c4v.y);
                __nv_bfloat16 hz = __float2bfloat16(c4v.z);
                __nv_bfloat16 hw = __float2bfloat16(c4v.w);
                Chi[i0] = pack_bf16(hx, hy);
                Chi[i1] = pack_bf16(hz, hw);
                Clo[i0] = pack_bf16(
                    __float2bfloat16(c4v.x - __bfloat162float(hx)),
                    __float2bfloat16(c4v.y - __bfloat162float(hy)));
                Clo[i1] = pack_bf16(
                    __float2bfloat16(c4v.z - __bfloat162float(hz)),
                    __float2bfloat16(c4v.w - __bfloat162float(hw)));
            } else {
                *reinterpret_cast<float2*>(C + (size_t)row * N + col) =
                    make_float2(acc[tm][tn].x, acc[tm][tn].y);
                *reinterpret_cast<float2*>(C + (size_t)(row + 8) * N + col) =
                    make_float2(acc[tm][tn].z, acc[tm][tn].w);
            }
        }
    }
}

// ===========================================================================
// bf16x3 mma flash attention, interleaved mma ordering.
// ===========================================================================
#define AST 36
#define TQH 0
#define TQL 4608
#define TB0 9216
#define TBSZ 9216
#define ATOT 27648

__device__ __forceinline__ uint32_t a_off(int lane)
{
    return (uint32_t)(((lane & 15) * AST + (lane >> 4) * 4) * 4);
}
__device__ __forceinline__ uint32_t b_off(int lane)
{
    return (uint32_t)((((lane & 7) + ((lane >> 4) << 3)) * AST +
                       ((lane >> 3) & 1) * 4) * 4);
}
__device__ __forceinline__ uint32_t v_off(int lane)
{
    return (uint32_t)(((lane & 15) * AST + (lane >> 4) * 4) * 4);
}

__global__ void __launch_bounds__(256, 2)
attn_mma_kernel(const uint32_t* __restrict__ qh, const uint32_t* __restrict__ ql,
                const uint32_t* __restrict__ kh, const uint32_t* __restrict__ kl,
                const uint32_t* __restrict__ vh, const uint32_t* __restrict__ vl,
                const int* __restrict__ mask,
                uint32_t* __restrict__ ohi, uint32_t* __restrict__ olo)
{
    extern __shared__ uint32_t smu[];
    const uint32_t sb = smem_u32(smu);

    const int tid  = threadIdx.x;
    const int lane = tid & 31;
    const int warp = tid >> 5;
    const int g    = lane >> 2;
    const int tig  = lane & 3;
    const int b    = blockIdx.y >> 4;
    const int h    = blockIdx.y & 15;
    const int q0   = blockIdx.x * 128;
    const int qb   = q0 + warp * 16;
    const uint32_t ao = a_off(lane);
    const uint32_t bo = b_off(lane);
    const uint32_t vo = v_off(lane);
    const size_t   bS = (size_t)b * S_;

    #pragma unroll
    for (int i = 0; i < 8; i++) {
        int idx = tid + i * 256;
        int hl = idx >> 10;
        int rem = idx & 1023;
        int r = rem >> 3, c = rem & 7;
        const uint32_t* src = (hl ? ql : qh) +
            (bS + q0 + r) * DP_ + h * 32 + c * 4;
        uint4 v = *reinterpret_cast<const uint4*>(src);
        *reinterpret_cast<uint4*>(smu + (hl ? TQL : TQH) + r * AST + c * 4) = v;
    }

    auto stage = [&](int kt, int bb) {
        const uint32_t tb = sb + (uint32_t)(TB0 + bb * TBSZ) * 4;
        #pragma unroll
        for (int i = 0; i < 8; i++) {
            int idx = tid + i * 256;
            int tv  = idx >> 10;
            int rem = idx & 1023;
            int hl  = rem >> 9;
            int r   = (rem >> 3) & 63;
            int c   = rem & 7;
            const uint32_t* src = (tv ? (hl ? vl : vh) : (hl ? kl : kh)) +
                (bS + kt + r) * DP_ + h * 32 + c * 4;
            uint32_t dst = tb + (uint32_t)((tv * 2 + hl) * 2304 +
                                           r * AST + c * 4) * 4;
            cpa16(dst, src);
        }
    };

    float4 oacc[8];
    #pragma unroll
    for (int i = 0; i < 8; i++) oacc[i] = make_float4(0.f, 0.f, 0.f, 0.f);
    float mrun0 = -1e30f, mrun1 = -1e30f, lrun0 = 0.f, lrun1 = 0.f;

    stage(0, 0);
    asm volatile("cp.async.commit_group;" ::: "memory");
    int pb = 0;

    for (int kt = 0; kt < S_; kt += 64) {
        __syncthreads();
        const bool more = (kt + 64 < S_);
        if (more) {
            stage(kt + 64, pb ^ 1);
            asm volatile("cp.async.commit_group;" ::: "memory");
            asm volatile("cp.async.wait_group 1;" ::: "memory");
        } else {
            asm volatile("cp.async.wait_group 0;" ::: "memory");
        }
        __syncthreads();

        const uint32_t tb  = sb + (uint32_t)(TB0 + pb * TBSZ) * 4;
        const uint32_t kbh = tb;
        const uint32_t kbl = tb + 2304u * 4;
        const uint32_t vbh = tb + 4608u * 4;
        const uint32_t vbl = tb + 6912u * 4;

        float4 sacc[8];
        #pragma unroll
        for (int j = 0; j < 8; j++) sacc[j] = make_float4(0.f, 0.f, 0.f, 0.f);

        #pragma unroll
        for (int ks = 0; ks < 4; ks++) {
            uint32_t aa = (uint32_t)(((warp * 16) * AST + ks * 8) * 4) + ao;
            uint32_t ah0, ah1, ah2, ah3, al0, al1, al2, al3;
            ldm_x4(ah0, ah1, ah2, ah3, sb + TQH * 4 + aa);
            ldm_x4(al0, al1, al2, al3, sb + TQL * 4 + aa);
            #pragma unroll
            for (int jp = 0; jp < 4; jp++) {
                uint32_t ba = (uint32_t)(((jp * 16) * AST + ks * 8) * 4) + bo;
                uint32_t bh0, bh1, bh2, bh3, bl0, bl1, bl2, bl3;
                ldm_x4(bh0, bh1, bh2, bh3, kbh + ba);
                ldm_x4(bl0, bl1, bl2, bl3, kbl + ba);
                // interleaved: hh,hh then hl,hl then lh,lh (distance 2; the
                // non-volatile mmas also pipeline across jp iterations)
                mma_bf16(sacc[2 * jp],     ah0, ah1, ah2, ah3, bh0, bh1);
                mma_bf16(sacc[2 * jp + 1], ah0, ah1, ah2, ah3, bh2, bh3);
                mma_bf16(sacc[2 * jp],     ah0, ah1, ah2, ah3, bl0, bl1);
                mma_bf16(sacc[2 * jp + 1], ah0, ah1, ah2, ah3, bl2, bl3);
                mma_bf16(sacc[2 * jp],     al0, al1, al2, al3, bh0, bh1);
                mma_bf16(sacc[2 * jp + 1], al0, al1, al2, al3, bh2, bh3);
            }
        }

        const size_t mrow0 = (bS + qb + g) * S_ + kt;
        const size_t mrow1 = mrow0 + 8 * S_;
        #pragma unroll
        for (int jn = 0; jn < 8; jn++) {
            int kc = jn * 8 + 2 * tig;
            int2 m0 = *reinterpret_cast<const int2*>(mask + mrow0 + kc);
            int2 m1 = *reinterpret_cast<const int2*>(mask + mrow1 + kc);
            sacc[jn].x = m0.x ? sacc[jn].x * 0.125f : -1e9f;
            sacc[jn].y = m0.y ? sacc[jn].y * 0.125f : -1e9f;
            sacc[jn].z = m1.x ? sacc[jn].z * 0.125f : -1e9f;
            sacc[jn].w = m1.y ? sacc[jn].w * 0.125f : -1e9f;
        }

        float rm0 = -1e30f, rm1 = -1e30f;
        #pragma unroll
        for (int jn = 0; jn < 8; jn++) {
            rm0 = fmaxf(rm0, fmaxf(sacc[jn].x, sacc[jn].y));
            rm1 = fmaxf(rm1, fmaxf(sacc[jn].z, sacc[jn].w));
        }
        rm0 = fmaxf(rm0, __shfl_xor_sync(0xffffffffu, rm0, 1));
        rm0 = fmaxf(rm0, __shfl_xor_sync(0xffffffffu, rm0, 2));
        rm1 = fmaxf(rm1, __shfl_xor_sync(0xffffffffu, rm1, 1));
        rm1 = fmaxf(rm1, __shfl_xor_sync(0xffffffffu, rm1, 2));

        float mnew0 = fmaxf(mrun0, rm0), mnew1 = fmaxf(mrun1, rm1);
        float corr0 = fexp(mrun0 - mnew0), corr1 = fexp(mrun1 - mnew1);
        #pragma unroll
        for (int dn = 0; dn < 8; dn++) {
            oacc[dn].x *= corr0; oacc[dn].y *= corr0;
            oacc[dn].z *= corr1; oacc[dn].w *= corr1;
        }
        float ls0 = 0.f, ls1 = 0.f;
        #pragma unroll
        for (int jn = 0; jn < 8; jn++) {
            sacc[jn].x = fexp(sacc[jn].x - mnew0);
            sacc[jn].y = fexp(sacc[jn].y - mnew0);
            sacc[jn].z = fexp(sacc[jn].z - mnew1);
            sacc[jn].w = fexp(sacc[jn].w - mnew1);
            ls0 += sacc[jn].x + sacc[jn].y;
            ls1 += sacc[jn].z + sacc[jn].w;
        }
        ls0 += __shfl_xor_sync(0xffffffffu, ls0, 1);
        ls0 += __shfl_xor_sync(0xffffffffu, ls0, 2);
        ls1 += __shfl_xor_sync(0xffffffffu, ls1, 1);
        ls1 += __shfl_xor_sync(0xffffffffu, ls1, 2);
        lrun0 = lrun0 * corr0 + ls0;
        lrun1 = lrun1 * corr1 + ls1;
        mrun0 = mnew0; mrun1 = mnew1;

        #pragma unroll
        for (int t = 0; t < 4; t++) {
            const float4 p0 = sacc[2 * t], p1 = sacc[2 * t + 1];
            __nv_bfloat16 h0x = __float2bfloat16(p0.x), h0y = __float2bfloat16(p0.y);
            __nv_bfloat16 h0z = __float2bfloat16(p0.z), h0w = __float2bfloat16(p0.w);
            __nv_bfloat16 h1x = __float2bfloat16(p1.x), h1y = __float2bfloat16(p1.y);
            __nv_bfloat16 h1z = __float2bfloat16(p1.z), h1w = __float2bfloat16(p1.w);
            uint32_t aph0 = pack_bf16(h0x, h0y);
            uint32_t aph1 = pack_bf16(h0z, h0w);
            uint32_t aph2 = pack_bf16(h1x, h1y);
            uint32_t aph3 = pack_bf16(h1z, h1w);
            uint32_t apl0 = pack_bf16(
                __float2bfloat16(p0.x - __bfloat162float(h0x)),
                __float2bfloat16(p0.y - __bfloat162float(h0y)));
            uint32_t apl1 = pack_bf16(
                __float2bfloat16(p0.z - __bfloat162float(h0z)),
                __float2bfloat16(p0.w - __bfloat162float(h0w)));
            uint32_t apl2 = pack_bf16(
                __float2bfloat16(p1.x - __bfloat162float(h1x)),
                __float2bfloat16(p1.y - __bfloat162float(h1y)));
            uint32_t apl3 = pack_bf16(
                __float2bfloat16(p1.z - __bfloat162float(h1z)),
                __float2bfloat16(p1.w - __bfloat162float(h1w)));
            #pragma unroll
            for (int dp = 0; dp < 4; dp++) {
                uint32_t ba = (uint32_t)(((t * 16) * AST + dp * 8) * 4) + vo;
                uint32_t vh0, vh1, vh2, vh3, vl0, vl1, vl2, vl3;
                ldm_x4_t(vh0, vh1, vh2, vh3, vbh + ba);
                ldm_x4_t(vl0, vl1, vl2, vl3, vbl + ba);
                mma_bf16(oacc[2 * dp],     aph0, aph1, aph2, aph3, vh0, vh1);
                mma_bf16(oacc[2 * dp + 1], aph0, aph1, aph2, aph3, vh2, vh3);
                mma_bf16(oacc[2 * dp],     aph0, aph1, aph2, aph3, vl0, vl1);
                mma_bf16(oacc[2 * dp + 1], aph0, aph1, aph2, aph3, vl2, vl3);
                mma_bf16(oacc[2 * dp],     apl0, apl1, apl2, apl3, vh0, vh1);
                mma_bf16(oacc[2 * dp + 1], apl0, apl1, apl2, apl3, vh2, vh3);
            }
        }
        pb ^= 1;
    }

    // ---- finalize: normalize and write split hi/lo ----
    const float inv0 = 1.f / lrun0, inv1 = 1.f / lrun1;
    const size_t r0 = (bS + qb + g) * DP_ + h * 32;
    const size_t r1 = r0 + 8 * DP_;
    #pragma unroll
    for (int dn = 0; dn < 8; dn++) {
        size_t i0 = r0 + dn * 4 + tig;
        size_t i1 = r1 + dn * 4 + tig;
        float x0 = oacc[dn].x * inv0, y0 = oacc[dn].y * inv0;
        float x1 = oacc[dn].z * inv1, y1 = oacc[dn].w * inv1;
        __nv_bfloat16 hx0 = __float2bfloat16(x0), hy0 = __float2bfloat16(y0);
        __nv_bfloat16 hx1 = __float2bfloat16(x1), hy1 = __float2bfloat16(y1);
        ohi[i0] = pack_bf16(hx0, hy0);
        ohi[i1] = pack_bf16(hx1, hy1);
        olo[i0] = pack_bf16(__float2bfloat16(x0 - __bfloat162float(hx0)),
                            __float2bfloat16(y0 - __bfloat162float(hy0)));
        olo[i1] = pack_bf16(__float2bfloat16(x1 - __bfloat162float(hx1)),
                            __float2bfloat16(y1 - __bfloat162float(hy1)));
    }
}

// ---------------------------------------------------------------------------
// Launch: graph-capturable, no allocations / syncs.
// ---------------------------------------------------------------------------
extern "C" void kernel_launch(void* const* d_in, const int* in_sizes, int n_in,
                              void* d_out, int out_size)
{
    const float* q    = (const float*)d_in[0];
    const float* k    = (const float*)d_in[1];
    const float* v    = (const float*)d_in[2];
    const int*   mask = (const int*)  d_in[3];
    const float* w_q  = (const float*)d_in[4];
    const float* w_k  = (const float*)d_in[5];
    const float* w_v  = (const float*)d_in[6];
    const float* w_o  = (const float*)d_in[7];
    float* out = (float*)d_out;

    uint32_t *xqh, *xql, *xkh, *xkl, *xvh, *xvl;
    uint32_t *wqh, *wql, *wkh, *wkl, *wvh, *wvl, *woh, *wol;
    uint32_t *qh, *ql, *kh, *kl, *vh, *vl, *ohv, *olv;
    cudaGetSymbolAddress((void**)&xqh, g_Xqh); cudaGetSymbolAddress((void**)&xql, g_Xql);
    cudaGetSymbolAddress((void**)&xkh, g_Xkh); cudaGetSymbolAddress((void**)&xkl, g_Xkl);
    cudaGetSymbolAddress((void**)&xvh, g_Xvh); cudaGetSymbolAddress((void**)&xvl, g_Xvl);
    cudaGetSymbolAddress((void**)&wqh, g_Wqh); cudaGetSymbolAddress((void**)&wql, g_Wql);
    cudaGetSymbolAddress((void**)&wkh, g_Wkh); cudaGetSymbolAddress((void**)&wkl, g_Wkl);
    cudaGetSymbolAddress((void**)&wvh, g_Wvh); cudaGetSymbolAddress((void**)&wvl, g_Wvl);
    cudaGetSymbolAddress((void**)&woh, g_Woh); cudaGetSymbolAddress((void**)&wol, g_Wol);
    cudaGetSymbolAddress((void**)&qh, g_Qh);   cudaGetSymbolAddress((void**)&ql, g_Ql);
    cudaGetSymbolAddress((void**)&kh, g_Kh);   cudaGetSymbolAddress((void**)&kl, g_Kl);
    cudaGetSymbolAddress((void**)&vh, g_Vh);   cudaGetSymbolAddress((void**)&vl, g_Vl);
    cudaGetSymbolAddress((void**)&ohv, g_Oh);  cudaGetSymbolAddress((void**)&olv, g_Ol);

    const int M = B_ * S_;
    const int n4in = M * D_ / 4;
    const int n4w  = D_ * D_ / 4;

    split_kernel<<<(n4in + 255) / 256, 256>>>(q, xqh, xql, n4in);
    split_kernel<<<(n4in + 255) / 256, 256>>>(k, xkh, xkl, n4in);
    split_kernel<<<(n4in + 255) / 256, 256>>>(v, xvh, xvl, n4in);
    split_kernel<<<(n4w + 255) / 256, 256>>>(w_q, wqh, wql, n4w);
    split_kernel<<<(n4w + 255) / 256, 256>>>(w_k, wkh, wkl, n4w);
    split_kernel<<<(n4w + 255) / 256, 256>>>(w_v, wvh, wvl, n4w);
    split_kernel<<<(n4w + 255) / 256, 256>>>(w_o, woh, wol, n4w);

    dim3 gemm_grid(D_ / 128, M / 128);
    const int gemm_smem = 2 * GSTG * (int)sizeof(uint32_t);
    cudaFuncSetAttribute(gemm_sp_kernel<true>,
                         cudaFuncAttributeMaxDynamicSharedMemorySize, gemm_smem);
    cudaFuncSetAttribute(gemm_sp_kernel<false>,
                         cudaFuncAttributeMaxDynamicSharedMemorySize, gemm_smem);

    gemm_sp_kernel<true><<<gemm_grid, 256, gemm_smem>>>(
        xqh, xql, wqh, wql, nullptr, qh, ql, M, D_);
    gemm_sp_kernel<true><<<gemm_grid, 256, gemm_smem>>>(
        xkh, xkl, wkh, wkl, nullptr, kh, kl, M, D_);
    gemm_sp_kernel<true><<<gemm_grid, 256, gemm_smem>>>(
        xvh, xvl, wvh, wvl, nullptr, vh, vl, M, D_);

    const int attn_smem = ATOT * (int)sizeof(uint32_t);
    cudaFuncSetAttribute(attn_mma_kernel,
                         cudaFuncAttributeMaxDynamicSharedMemorySize, attn_smem);
    dim3 attn_grid(S_ / 128, B_ * H_);
    attn_mma_kernel<<<attn_grid, 256, attn_smem>>>(
        qh, ql, kh, kl, vh, vl, mask, ohv, olv);

    gemm_sp_kernel<false><<<gemm_grid, 256, gemm_smem>>>(
        ohv, olv, woh, wol, out, nullptr, nullptr, M, D_);
}

// round 17
// speedup vs baseline: 1.3623x; 1.3623x over previous
#include <cuda_runtime.h>
#include <cuda_fp16.h>
#include <cstdint>

#define B_  4
#define S_  2048
#define D_  1024
#define H_  16
#define DK_ 64
#define DP_ 512   // D/2 packed u32 (fp16 pairs) per row

// Scratch (__device__ globals; no cudaMalloc allowed).
// Activations (A-operands): fp16 h only. Weights / K / V (B-operands): fp16 h+l.
__device__ uint32_t g_Xq[(size_t)B_ * S_ * DP_];    // split input q (h)
__device__ uint32_t g_Xk[(size_t)B_ * S_ * DP_];    // split input k (h)
__device__ uint32_t g_Xv[(size_t)B_ * S_ * DP_];    // split input v (h)
__device__ uint32_t g_Wqh[(size_t)D_ * DP_];
__device__ uint32_t g_Wql[(size_t)D_ * DP_];
__device__ uint32_t g_Wkh[(size_t)D_ * DP_];
__device__ uint32_t g_Wkl[(size_t)D_ * DP_];
__device__ uint32_t g_Wvh[(size_t)D_ * DP_];
__device__ uint32_t g_Wvl[(size_t)D_ * DP_];
__device__ uint32_t g_Woh[(size_t)D_ * DP_];
__device__ uint32_t g_Wol[(size_t)D_ * DP_];
__device__ uint32_t g_Qp[(size_t)B_ * S_ * DP_];    // projected Q (h only)
__device__ uint32_t g_Kh[(size_t)B_ * S_ * DP_];    // projected K (h+l)
__device__ uint32_t g_Kl[(size_t)B_ * S_ * DP_];
__device__ uint32_t g_Vh[(size_t)B_ * S_ * DP_];    // projected V (h+l)
__device__ uint32_t g_Vl[(size_t)B_ * S_ * DP_];
__device__ uint32_t g_Oa[(size_t)B_ * S_ * DP_];    // attn out (h only)

// ===========================================================================
// Common helpers
// ===========================================================================
__device__ __forceinline__ uint32_t smem_u32(const void* p)
{
    uint32_t a;
    asm("{ .reg .u64 t; cvta.to.shared.u64 t, %1; cvt.u32.u64 %0, t; }"
        : "=r"(a) : "l"(p));
    return a;
}

__device__ __forceinline__ uint32_t pack_f16(__half a, __half b)
{
    return (uint32_t)__half_as_ushort(a) | ((uint32_t)__half_as_ushort(b) << 16);
}

__device__ __forceinline__ void mma_f16(float4& c,
    uint32_t a0, uint32_t a1, uint32_t a2, uint32_t a3,
    uint32_t b0, uint32_t b1)
{
    asm("mma.sync.aligned.m16n8k16.row.col.f32.f16.f16.f32 "
        "{%0,%1,%2,%3}, {%4,%5,%6,%7}, {%8,%9}, {%0,%1,%2,%3};"
        : "+f"(c.x), "+f"(c.y), "+f"(c.z), "+f"(c.w)
        : "r"(a0), "r"(a1), "r"(a2), "r"(a3), "r"(b0), "r"(b1));
}

__device__ __forceinline__ void ldm_x4(uint32_t& r0, uint32_t& r1,
                                       uint32_t& r2, uint32_t& r3, uint32_t a)
{
    asm volatile(
        "ldmatrix.sync.aligned.m8n8.x4.shared.b16 {%0,%1,%2,%3}, [%4];"
        : "=r"(r0), "=r"(r1), "=r"(r2), "=r"(r3) : "r"(a));
}

__device__ __forceinline__ void ldm_x4_t(uint32_t& r0, uint32_t& r1,
                                         uint32_t& r2, uint32_t& r3, uint32_t a)
{
    asm volatile(
        "ldmatrix.sync.aligned.m8n8.x4.trans.shared.b16 {%0,%1,%2,%3}, [%4];"
        : "=r"(r0), "=r"(r1), "=r"(r2), "=r"(r3) : "r"(a));
}

__device__ __forceinline__ void cpa16(uint32_t dst, const void* src)
{
    asm volatile("cp.async.ca.shared.global [%0], [%1], 16;"
                 :: "r"(dst), "l"(src) : "memory");
}

// Fast exp on the FMA pipe (no MUFU).
__device__ __forceinline__ float fexp(float x)
{
    float t = fmaxf(x * 1.4426950408889634f, -126.0f);
    float z = t + 12582912.0f;
    int  ei = __float_as_int(z) - 0x4B400000;
    float f = t - (z - 12582912.0f);
    float p = fmaf(0.0013333558f, f, 0.0096181291f);
    p = fmaf(p, f, 0.0555041087f);
    p = fmaf(p, f, 0.2402265069f);
    p = fmaf(p, f, 0.6931471806f);
    p = fmaf(p, f, 1.0f);
    return __int_as_float(__float_as_int(p) + (ei << 23));
}

// ===========================================================================
// Split kernels: fp32 -> fp16 h (acts) / h+l (weights), memory-bound.
// ===========================================================================
__global__ void __launch_bounds__(256)
split_h_kernel(const float* __restrict__ src, uint32_t* __restrict__ hi, int n4)
{
    int i = blockIdx.x * 256 + threadIdx.x;
    if (i >= n4) return;
    float4 v = reinterpret_cast<const float4*>(src)[i];
    reinterpret_cast<uint2*>(hi)[i] = make_uint2(
        pack_f16(__float2half_rn(v.x), __float2half_rn(v.y)),
        pack_f16(__float2half_rn(v.z), __float2half_rn(v.w)));
}

__global__ void __launch_bounds__(256)
split_hl_kernel(const float* __restrict__ src, uint32_t* __restrict__ hi,
                uint32_t* __restrict__ lo, int n4)
{
    int i = blockIdx.x * 256 + threadIdx.x;
    if (i >= n4) return;
    float4 v = reinterpret_cast<const float4*>(src)[i];
    __half hx = __float2half_rn(v.x), hy = __float2half_rn(v.y);
    __half hz = __float2half_rn(v.z), hw = __float2half_rn(v.w);
    reinterpret_cast<uint2*>(hi)[i] =
        make_uint2(pack_f16(hx, hy), pack_f16(hz, hw));
    reinterpret_cast<uint2*>(lo)[i] = make_uint2(
        pack_f16(__float2half_rn(v.x - __half2float(hx)),
                 __float2half_rn(v.y - __half2float(hy))),
        pack_f16(__float2half_rn(v.z - __half2float(hz)),
                 __float2half_rn(v.w - __half2float(hw))));
}

// ===========================================================================
// fp16x2 GEMM: C = A * B^T ~= Ah*Bh + Ah*Bl (A residual dropped, ~2^-12).
// BK=32, cp.async double-buffered, ldmatrix frags.
// smem: 2 stages x 3 bufs (Ah, Bh, Bl) x 128 x 20 u32 = 61440 B.
// EPI: 0 = fp32 C, 1 = fp16 h only, 2 = fp16 h+l.
// ===========================================================================
#define GST2 20
#define GBUF (128 * GST2)
#define GSTG (3 * GBUF)

__device__ __forceinline__ uint32_t a_off2(int lane)
{
    return (uint32_t)(((lane & 15) * GST2 + (lane >> 4) * 4) * 4);
}
__device__ __forceinline__ uint32_t b_off2(int lane)
{
    return (uint32_t)((((lane & 7) + ((lane >> 4) << 3)) * GST2 +
                       ((lane >> 3) & 1) * 4) * 4);
}

template<int EPI>
__global__ void __launch_bounds__(256, 2)
gemm_f16_kernel(const uint32_t* __restrict__ Ahg,
                const uint32_t* __restrict__ Bhg, const uint32_t* __restrict__ Blg,
                float* __restrict__ C, uint32_t* __restrict__ Chi,
                uint32_t* __restrict__ Clo, int M, int N)
{
    extern __shared__ uint32_t smu[];
    const uint32_t sb = smem_u32(smu);

    const int tid  = threadIdx.x;
    const int lane = tid & 31;
    const int warp = tid >> 5;
    const int g    = lane >> 2;
    const int tig  = lane & 3;
    const int wm   = (warp >> 2) * 64;
    const int wn   = (warp & 3) * 32;
    const int m0   = blockIdx.y * 128;
    const int n0   = blockIdx.x * 128;
    const uint32_t ao = a_off2(lane);
    const uint32_t bo = b_off2(lane);

    auto stage = [&](int kc, int ss) {
        const uint32_t tb = sb + (uint32_t)(ss * GSTG) * 4;
        #pragma unroll
        for (int i = 0; i < 6; i++) {
            int idx = tid + i * 256;       // 0..1535
            int bf  = idx >> 9;            // 0 Ah, 1 Bh, 2 Bl
            int rem = idx & 511;
            int r   = rem >> 2;
            int c   = (rem & 3) * 4;
            const uint32_t* base =
                (bf == 0) ? Ahg + (size_t)(m0 + r) * DP_ :
                (bf == 1) ? Bhg + (size_t)(n0 + r) * DP_ :
                            Blg + (size_t)(n0 + r) * DP_;
            cpa16(tb + (uint32_t)(bf * GBUF + r * GST2 + c) * 4,
                  base + kc + c);
        }
    };

    float4 acc[4][4];
    #pragma unroll
    for (int i = 0; i < 4; i++)
        #pragma unroll
        for (int j = 0; j < 4; j++) acc[i][j] = make_float4(0.f, 0.f, 0.f, 0.f);

    stage(0, 0);
    asm volatile("cp.async.commit_group;" ::: "memory");
    int ps = 0;

    for (int kc = 0; kc < DP_; kc += 16) {
        __syncthreads();
        const bool more = (kc + 16 < DP_);
        if (more) {
            stage(kc + 16, ps ^ 1);
            asm volatile("cp.async.commit_group;" ::: "memory");
            asm volatile("cp.async.wait_group 1;" ::: "memory");
        } else {
            asm volatile("cp.async.wait_group 0;" ::: "memory");
        }
        __syncthreads();

        const uint32_t tb  = sb + (uint32_t)(ps * GSTG) * 4;
        const uint32_t sAh = tb;
        const uint32_t sBh = tb + (uint32_t)GBUF * 4;
        const uint32_t sBl = tb + (uint32_t)(2 * GBUF) * 4;

        #pragma unroll
        for (int ks = 0; ks < 2; ks++) {
            uint32_t bh[4][2], bl[4][2];
            #pragma unroll
            for (int tp = 0; tp < 2; tp++) {
                uint32_t ba = (uint32_t)(((wn + tp * 16) * GST2 + ks * 8) * 4) + bo;
                ldm_x4(bh[2 * tp][0], bh[2 * tp][1],
                       bh[2 * tp + 1][0], bh[2 * tp + 1][1], sBh + ba);
                ldm_x4(bl[2 * tp][0], bl[2 * tp][1],
                       bl[2 * tp + 1][0], bl[2 * tp + 1][1], sBl + ba);
            }
            #pragma unroll
            for (int tm = 0; tm < 4; tm++) {
                uint32_t aa = (uint32_t)(((wm + tm * 16) * GST2 + ks * 8) * 4) + ao;
                uint32_t ah0, ah1, ah2, ah3;
                ldm_x4(ah0, ah1, ah2, ah3, sAh + aa);
                #pragma unroll
                for (int tn = 0; tn < 4; tn++)
                    mma_f16(acc[tm][tn], ah0, ah1, ah2, ah3,
                            bh[tn][0], bh[tn][1]);
                #pragma unroll
                for (int tn = 0; tn < 4; tn++)
                    mma_f16(acc[tm][tn], ah0, ah1, ah2, ah3,
                            bl[tn][0], bl[tn][1]);
            }
        }
        ps ^= 1;
    }

    #pragma unroll
    for (int tm = 0; tm < 4; tm++) {
        #pragma unroll
        for (int tn = 0; tn < 4; tn++) {
            int row = m0 + wm + tm * 16 + g;
            int col = n0 + wn + tn * 8 + 2 * tig;
            float4 c4v = acc[tm][tn];
            if (EPI == 0) {
                *reinterpret_cast<float2*>(C + (size_t)row * N + col) =
                    make_float2(c4v.x, c4v.y);
                *reinterpret_cast<float2*>(C + (size_t)(row + 8) * N + col) =
                    make_float2(c4v.z, c4v.w);
            } else {
                size_t i0 = (size_t)row * DP_ + (col >> 1);
                size_t i1 = (size_t)(row + 8) * DP_ + (col >> 1);
                __half hx = __float2half_rn(c4v.x), hy = __float2half_rn(c4v.y);
                __half hz = __float2half_rn(c4v.z), hw = __float2half_rn(c4v.w);
                Chi[i0] = pack_f16(hx, hy);
                Chi[i1] = pack_f16(hz, hw);
                if (EPI == 2) {
                    Clo[i0] = pack_f16(
                        __float2half_rn(c4v.x - __half2float(hx)),
                        __float2half_rn(c4v.y - __half2float(hy)));
                    Clo[i1] = pack_f16(
                        __float2half_rn(c4v.z - __half2float(hz)),
                        __float2half_rn(c4v.w - __half2float(hw)));
                }
            }
        }
    }
}

// ===========================================================================
// fp16x2 mma flash attention. Q/P h only; K/V h+l.
// smem (u32): Q 4608 | 2 x [Kh 2304 | Kl 2304 | Vh 2304 | Vl 2304]
//  = 23040 u32 = 92160 B -> 2 CTAs/SM.
// ===========================================================================
#define AST 36
#define TB0 4608
#define TBSZ 9216
#define ATOT 23040

__device__ __forceinline__ uint32_t a_off(int lane)
{
    return (uint32_t)(((lane & 15) * AST + (lane >> 4) * 4) * 4);
}
__device__ __forceinline__ uint32_t b_off(int lane)
{
    return (uint32_t)((((lane & 7) + ((lane >> 4) << 3)) * AST +
                       ((lane >> 3) & 1) * 4) * 4);
}
__device__ __forceinline__ uint32_t v_off(int lane)
{
    return (uint32_t)(((lane & 15) * AST + (lane >> 4) * 4) * 4);
}

__global__ void __launch_bounds__(256, 2)
attn_mma_kernel(const uint32_t* __restrict__ qp,
                const uint32_t* __restrict__ kh, const uint32_t* __restrict__ kl,
                const uint32_t* __restrict__ vh, const uint32_t* __restrict__ vl,
                const int* __restrict__ mask, uint32_t* __restrict__ oh)
{
    extern __shared__ uint32_t smu[];
    const uint32_t sb = smem_u32(smu);

    const int tid  = threadIdx.x;
    const int lane = tid & 31;
    const int warp = tid >> 5;
    const int g    = lane >> 2;
    const int tig  = lane & 3;
    const int b    = blockIdx.y >> 4;
    const int h    = blockIdx.y & 15;
    const int q0   = blockIdx.x * 128;
    const int qb   = q0 + warp * 16;
    const uint32_t ao = a_off(lane);
    const uint32_t bo = b_off(lane);
    const uint32_t vo = v_off(lane);
    const size_t   bS = (size_t)b * S_;

    // ---- stage Q tile [128 rows x 32 u32] h only ----
    #pragma unroll
    for (int i = 0; i < 4; i++) {
        int idx = tid + i * 256;         // 0..1023
        int r = idx >> 3, c = idx & 7;
        const uint32_t* src = qp + (bS + q0 + r) * DP_ + h * 32 + c * 4;
        *reinterpret_cast<uint4*>(smu + r * AST + c * 4) =
            *reinterpret_cast<const uint4*>(src);
    }

    auto stage = [&](int kt, int bb) {
        const uint32_t tb = sb + (uint32_t)(TB0 + bb * TBSZ) * 4;
        #pragma unroll
        for (int i = 0; i < 8; i++) {
            int idx = tid + i * 256;
            int tv  = idx >> 10;         // 0 K, 1 V
            int rem = idx & 1023;
            int hl  = rem >> 9;          // 0 h, 1 l
            int r   = (rem >> 3) & 63;
            int c   = rem & 7;
            const uint32_t* src = (tv ? (hl ? vl : vh) : (hl ? kl : kh)) +
                (bS + kt + r) * DP_ + h * 32 + c * 4;
            uint32_t dst = tb + (uint32_t)((tv * 2 + hl) * 2304 +
                                           r * AST + c * 4) * 4;
            cpa16(dst, src);
        }
    };

    float4 oacc[8];
    #pragma unroll
    for (int i = 0; i < 8; i++) oacc[i] = make_float4(0.f, 0.f, 0.f, 0.f);
    float mrun0 = -1e30f, mrun1 = -1e30f, lrun0 = 0.f, lrun1 = 0.f;

    stage(0, 0);
    asm volatile("cp.async.commit_group;" ::: "memory");
    int pb = 0;

    for (int kt = 0; kt < S_; kt += 64) {
        __syncthreads();
        const bool more = (kt + 64 < S_);
        if (more) {
            stage(kt + 64, pb ^ 1);
            asm volatile("cp.async.commit_group;" ::: "memory");
            asm volatile("cp.async.wait_group 1;" ::: "memory");
        } else {
            asm volatile("cp.async.wait_group 0;" ::: "memory");
        }
        __syncthreads();

        const uint32_t tb  = sb + (uint32_t)(TB0 + pb * TBSZ) * 4;
        const uint32_t kbh = tb;
        const uint32_t kbl = tb + 2304u * 4;
        const uint32_t vbh = tb + 4608u * 4;
        const uint32_t vbl = tb + 6912u * 4;

        // ---- S = Q K^T : Qh * (Kh + Kl) ----
        float4 sacc[8];
        #pragma unroll
        for (int j = 0; j < 8; j++) sacc[j] = make_float4(0.f, 0.f, 0.f, 0.f);

        #pragma unroll
        for (int ks = 0; ks < 4; ks++) {
            uint32_t aa = (uint32_t)(((warp * 16) * AST + ks * 8) * 4) + ao;
            uint32_t ah0, ah1, ah2, ah3;
            ldm_x4(ah0, ah1, ah2, ah3, sb + aa);
            #pragma unroll
            for (int jp = 0; jp < 4; jp++) {
                uint32_t ba = (uint32_t)(((jp * 16) * AST + ks * 8) * 4) + bo;
                uint32_t bh0, bh1, bh2, bh3, bl0, bl1, bl2, bl3;
                ldm_x4(bh0, bh1, bh2, bh3, kbh + ba);
                ldm_x4(bl0, bl1, bl2, bl3, kbl + ba);
                mma_f16(sacc[2 * jp],     ah0, ah1, ah2, ah3, bh0, bh1);
                mma_f16(sacc[2 * jp + 1], ah0, ah1, ah2, ah3, bh2, bh3);
                mma_f16(sacc[2 * jp],     ah0, ah1, ah2, ah3, bl0, bl1);
                mma_f16(sacc[2 * jp + 1], ah0, ah1, ah2, ah3, bl2, bl3);
            }
        }

        // ---- scale + mask ----
        const size_t mrow0 = (bS + qb + g) * S_ + kt;
        const size_t mrow1 = mrow0 + 8 * S_;
        #pragma unroll
        for (int jn = 0; jn < 8; jn++) {
            int kc = jn * 8 + 2 * tig;
            int2 m0 = *reinterpret_cast<const int2*>(mask + mrow0 + kc);
            int2 m1 = *reinterpret_cast<const int2*>(mask + mrow1 + kc);
            sacc[jn].x = m0.x ? sacc[jn].x * 0.125f : -1e9f;
            sacc[jn].y = m0.y ? sacc[jn].y * 0.125f : -1e9f;
            sacc[jn].z = m1.x ? sacc[jn].z * 0.125f : -1e9f;
            sacc[jn].w = m1.y ? sacc[jn].w * 0.125f : -1e9f;
        }

        // ---- online softmax (rows g and g+8) ----
        float rm0 = -1e30f, rm1 = -1e30f;
        #pragma unroll
        for (int jn = 0; jn < 8; jn++) {
            rm0 = fmaxf(rm0, fmaxf(sacc[jn].x, sacc[jn].y));
            rm1 = fmaxf(rm1, fmaxf(sacc[jn].z, sacc[jn].w));
        }
        rm0 = fmaxf(rm0, __shfl_xor_sync(0xffffffffu, rm0, 1));
        rm0 = fmaxf(rm0, __shfl_xor_sync(0xffffffffu, rm0, 2));
        rm1 = fmaxf(rm1, __shfl_xor_sync(0xffffffffu, rm1, 1));
        rm1 = fmaxf(rm1, __shfl_xor_sync(0xffffffffu, rm1, 2));

        float mnew0 = fmaxf(mrun0, rm0), mnew1 = fmaxf(mrun1, rm1);
        float corr0 = fexp(mrun0 - mnew0), corr1 = fexp(mrun1 - mnew1);
        #pragma unroll
        for (int dn = 0; dn < 8; dn++) {
            oacc[dn].x *= corr0; oacc[dn].y *= corr0;
            oacc[dn].z *= corr1; oacc[dn].w *= corr1;
        }
        float ls0 = 0.f, ls1 = 0.f;
        #pragma unroll
        for (int jn = 0; jn < 8; jn++) {
            sacc[jn].x = fexp(sacc[jn].x - mnew0);
            sacc[jn].y = fexp(sacc[jn].y - mnew0);
            sacc[jn].z = fexp(sacc[jn].z - mnew1);
            sacc[jn].w = fexp(sacc[jn].w - mnew1);
            ls0 += sacc[jn].x + sacc[jn].y;
            ls1 += sacc[jn].z + sacc[jn].w;
        }
        ls0 += __shfl_xor_sync(0xffffffffu, ls0, 1);
        ls0 += __shfl_xor_sync(0xffffffffu, ls0, 2);
        ls1 += __shfl_xor_sync(0xffffffffu, ls1, 1);
        ls1 += __shfl_xor_sync(0xffffffffu, ls1, 2);
        lrun0 = lrun0 * corr0 + ls0;
        lrun1 = lrun1 * corr1 + ls1;
        mrun0 = mnew0; mrun1 = mnew1;

        // ---- O += P V : Ph * (Vh + Vl), P fp16 h only ----
        #pragma unroll
        for (int t = 0; t < 4; t++) {
            const float4 p0 = sacc[2 * t], p1 = sacc[2 * t + 1];
            uint32_t aph0 = pack_f16(__float2half_rn(p0.x), __float2half_rn(p0.y));
            uint32_t aph1 = pack_f16(__float2half_rn(p0.z), __float2half_rn(p0.w));
            uint32_t aph2 = pack_f16(__float2half_rn(p1.x), __float2half_rn(p1.y));
            uint32_t aph3 = pack_f16(__float2half_rn(p1.z), __float2half_rn(p1.w));
            #pragma unroll
            for (int dp = 0; dp < 4; dp++) {
                uint32_t ba = (uint32_t)(((t * 16) * AST + dp * 8) * 4) + vo;
                uint32_t vh0, vh1, vh2, vh3, vl0, vl1, vl2, vl3;
                ldm_x4_t(vh0, vh1, vh2, vh3, vbh + ba);
                ldm_x4_t(vl0, vl1, vl2, vl3, vbl + ba);
                mma_f16(oacc[2 * dp],     aph0, aph1, aph2, aph3, vh0, vh1);
                mma_f16(oacc[2 * dp + 1], aph0, aph1, aph2, aph3, vh2, vh3);
                mma_f16(oacc[2 * dp],     aph0, aph1, aph2, aph3, vl0, vl1);
                mma_f16(oacc[2 * dp + 1], aph0, aph1, aph2, aph3, vl2, vl3);
            }
        }
        pb ^= 1;
    }

    // ---- finalize: normalize and write fp16 h ----
    const float inv0 = 1.f / lrun0, inv1 = 1.f / lrun1;
    const size_t r0 = (bS + qb + g) * DP_ + h * 32;
    const size_t r1 = r0 + 8 * DP_;
    #pragma unroll
    for (int dn = 0; dn < 8; dn++) {
        size_t i0 = r0 + dn * 4 + tig;
        size_t i1 = r1 + dn * 4 + tig;
        oh[i0] = pack_f16(__float2half_rn(oacc[dn].x * inv0),
                          __float2half_rn(oacc[dn].y * inv0));
        oh[i1] = pack_f16(__float2half_rn(oacc[dn].z * inv1),
                          __float2half_rn(oacc[dn].w * inv1));
    }
}

// ---------------------------------------------------------------------------
// Launch: graph-capturable, no allocations / syncs.
// ---------------------------------------------------------------------------
extern "C" void kernel_launch(void* const* d_in, const int* in_sizes, int n_in,
                              void* d_out, int out_size)
{
    const float* q    = (const float*)d_in[0];
    const float* k    = (const float*)d_in[1];
    const float* v    = (const float*)d_in[2];
    const int*   mask = (const int*)  d_in[3];
    const float* w_q  = (const float*)d_in[4];
    const float* w_k  = (const float*)d_in[5];
    const float* w_v  = (const float*)d_in[6];
    const float* w_o  = (const float*)d_in[7];
    float* out = (float*)d_out;

    uint32_t *xq, *xk, *xv;
    uint32_t *wqh, *wql, *wkh, *wkl, *wvh, *wvl, *woh, *wol;
    uint32_t *qpv, *khv, *klv, *vhv, *vlv, *oav;
    cudaGetSymbolAddress((void**)&xq, g_Xq);
    cudaGetSymbolAddress((void**)&xk, g_Xk);
    cudaGetSymbolAddress((void**)&xv, g_Xv);
    cudaGetSymbolAddress((void**)&wqh, g_Wqh); cudaGetSymbolAddress((void**)&wql, g_Wql);
    cudaGetSymbolAddress((void**)&wkh, g_Wkh); cudaGetSymbolAddress((void**)&wkl, g_Wkl);
    cudaGetSymbolAddress((void**)&wvh, g_Wvh); cudaGetSymbolAddress((void**)&wvl, g_Wvl);
    cudaGetSymbolAddress((void**)&woh, g_Woh); cudaGetSymbolAddress((void**)&wol, g_Wol);
    cudaGetSymbolAddress((void**)&qpv, g_Qp);
    cudaGetSymbolAddress((void**)&khv, g_Kh);  cudaGetSymbolAddress((void**)&klv, g_Kl);
    cudaGetSymbolAddress((void**)&vhv, g_Vh);  cudaGetSymbolAddress((void**)&vlv, g_Vl);
    cudaGetSymbolAddress((void**)&oav, g_Oa);

    const int M = B_ * S_;
    const int n4in = M * D_ / 4;
    const int n4w  = D_ * D_ / 4;

    split_h_kernel<<<(n4in + 255) / 256, 256>>>(q, xq, n4in);
    split_h_kernel<<<(n4in + 255) / 256, 256>>>(k, xk, n4in);
    split_h_kernel<<<(n4in + 255) / 256, 256>>>(v, xv, n4in);
    split_hl_kernel<<<(n4w + 255) / 256, 256>>>(w_q, wqh, wql, n4w);
    split_hl_kernel<<<(n4w + 255) / 256, 256>>>(w_k, wkh, wkl, n4w);
    split_hl_kernel<<<(n4w + 255) / 256, 256>>>(w_v, wvh, wvl, n4w);
    split_hl_kernel<<<(n4w + 255) / 256, 256>>>(w_o, woh, wol, n4w);

    dim3 gemm_grid(D_ / 128, M / 128);
    const int gemm_smem = 2 * GSTG * (int)sizeof(uint32_t);   // 61440 B
    cudaFuncSetAttribute(gemm_f16_kernel<0>,
                         cudaFuncAttributeMaxDynamicSharedMemorySize, gemm_smem);
    cudaFuncSetAttribute(gemm_f16_kernel<1>,
                         cudaFuncAttributeMaxDynamicSharedMemorySize, gemm_smem);
    cudaFuncSetAttribute(gemm_f16_kernel<2>,
                         cudaFuncAttributeMaxDynamicSharedMemorySize, gemm_smem);

    // Q projection -> h only (A-operand of QK^T)
    gemm_f16_kernel<1><<<gemm_grid, 256, gemm_smem>>>(
        xq, wqh, wql, nullptr, qpv, nullptr, M, D_);
    // K projection -> h+l (B-operand of QK^T)
    gemm_f16_kernel<2><<<gemm_grid, 256, gemm_smem>>>(
        xk, wkh, wkl, nullptr, khv, klv, M, D_);
    // V projection -> h+l (B-operand of PV)
    gemm_f16_kernel<2><<<gemm_grid, 256, gemm_smem>>>(
        xv, wvh, wvl, nullptr, vhv, vlv, M, D_);

    const int attn_smem = ATOT * (int)sizeof(uint32_t);       // 92160 B
    cudaFuncSetAttribute(attn_mma_kernel,
                         cudaFuncAttributeMaxDynamicSharedMemorySize, attn_smem);
    dim3 attn_grid(S_ / 128, B_ * H_);
    attn_mma_kernel<<<attn_grid, 256, attn_smem>>>(
        qpv, khv, klv, vhv, vlv, mask, oav);

    // out projection: fp32 epilogue to harness output
    gemm_f16_kernel<0><<<gemm_grid, 256, gemm_smem>>>(
        oav, woh, wol, out, nullptr, nullptr, M, D_);
}